// round 6
// baseline (speedup 1.0000x reference)
#include <cuda_runtime.h>
#include <cuda_bf16.h>
#include <cstdint>

#define NROWS 262144
#define DD 128
#define HH 16
#define EE 21

#define THREADS 256
#define RPT 4                     // rows per thread, full 16 h each
#define M_TILE 1024
#define CHUNK_D 8
#define NPHASE 16                 // 128 / 8
#define RING 6
#define LOOK 4
#define GRID_MAIN 148

#define XCHUNK_BYTES (M_TILE * CHUNK_D * 4)   // 32768
#define WB_FLOATS (DD * HH)                   // 2048
#define WB_BYTES (WB_FLOATS * 4)              // 8192
#define SMEM_BYTES (RING * XCHUNK_BYTES + 2 * WB_BYTES + 2 * 160 + 2 * M_TILE * 4)

__device__ int g_counts[EE];
__device__ int g_cursor[EE];
__device__ int g_offsets[EE + 1];
__device__ int g_tileOff[EE + 1];
__device__ int g_numTiles;
__device__ int g_perm[NROWS];

// ---------------- K1: histogram (int4 vectorized) ----------------
__global__ void k_hist(const int* __restrict__ sid) {
    __shared__ int sh[EE];
    int tid = threadIdx.x;
    if (tid < EE) sh[tid] = 0;
    __syncthreads();
    int4 v = ((const int4*)sid)[blockIdx.x * blockDim.x + tid];
    atomicAdd(&sh[v.x], 1);
    atomicAdd(&sh[v.y], 1);
    atomicAdd(&sh[v.z], 1);
    atomicAdd(&sh[v.w], 1);
    __syncthreads();
    if (tid < EE) atomicAdd(&g_counts[tid], sh[tid]);
}

// ---------------- K2: warp scan (+ zero counts for next replay) ----------
__global__ void k_scan() {
    int t = threadIdx.x;
    int c  = (t < EE) ? g_counts[t] : 0;
    int tl = (c + M_TILE - 1) / M_TILE;
    int ic = c, it = tl;
    #pragma unroll
    for (int d = 1; d < 32; d <<= 1) {
        int vc = __shfl_up_sync(0xFFFFFFFFu, ic, d);
        int vt = __shfl_up_sync(0xFFFFFFFFu, it, d);
        if (t >= d) { ic += vc; it += vt; }
    }
    if (t < EE) {
        g_offsets[t] = ic - c;
        g_cursor[t]  = ic - c;
        g_tileOff[t] = it - tl;
        g_counts[t]  = 0;
    }
    int totC = __shfl_sync(0xFFFFFFFFu, ic, EE - 1);
    int totT = __shfl_sync(0xFFFFFFFFu, it, EE - 1);
    if (t == 0) {
        g_offsets[EE] = totC;
        g_tileOff[EE] = totT;
        g_numTiles = totT;
    }
}

// ---------------- K3: scatter ----------------
__global__ void k_scatter(const int* __restrict__ sid) {
    __shared__ int sHist[EE];
    __shared__ int sBase[EE];
    int tid = threadIdx.x;
    if (tid < EE) sHist[tid] = 0;
    __syncthreads();
    int gid = blockIdx.x * blockDim.x + tid;
    int e = sid[gid];
    int myIdx = atomicAdd(&sHist[e], 1);
    __syncthreads();
    if (tid < EE) sBase[tid] = atomicAdd(&g_cursor[tid], sHist[tid]);
    __syncthreads();
    g_perm[sBase[e] + myIdx] = gid;
}

// ---------------- K4: deep-pipelined persistent expert MLP ----------------
__device__ __forceinline__ void cp_async16(uint32_t dst, const void* src) {
    asm volatile("cp.async.cg.shared.global [%0], [%1], 16;\n" :: "r"(dst), "l"(src));
}
__device__ __forceinline__ void cp_async4(uint32_t dst, const void* src) {
    asm volatile("cp.async.ca.shared.global [%0], [%1], 4;\n" :: "r"(dst), "l"(src));
}
#define CP_COMMIT() asm volatile("cp.async.commit_group;" ::: "memory")
#define CP_WAIT4()  asm volatile("cp.async.wait_group 4;" ::: "memory")
#define FMA2(acc, a, b) asm("fma.rn.f32x2 %0, %1, %2, %0;" : "+l"(acc) : "l"(a), "l"(b))

__device__ __forceinline__ unsigned long long bcast2(float f) {
    unsigned long long r;
    asm("mov.b64 %0, {%1,%1};" : "=l"(r) : "f"(f));
    return r;
}

__global__ __launch_bounds__(THREADS, 1)
void k_main(const float* __restrict__ x,
            const float* __restrict__ W1,
            const float* __restrict__ b1,
            const float* __restrict__ W2,
            const float* __restrict__ b2,
            float* __restrict__ out)
{
    extern __shared__ float smem[];
    float* xs  = smem;                                  // RING x 32KB chunk buffers
    float* wb  = xs + RING * (XCHUNK_BYTES / 4);        // 2 x [128 d][16 h]
    float* wx  = wb + 2 * WB_FLOATS;                    // 2 x 40 (b1, w2, b2)
    int*  sRow = (int*)(wx + 2 * 40);                   // 2 x 1024

    int nT = g_numTiles;
    int q = (nT + GRID_MAIN - 1) / GRID_MAIN;
    int t0 = blockIdx.x * q;
    int t1 = t0 + q; if (t1 > nT) t1 = nT;
    if (t0 >= t1) return;

    int tid = threadIdx.x;
    uint32_t xs_sh = (uint32_t)__cvta_generic_to_shared(xs);
    uint32_t wb_sh = (uint32_t)__cvta_generic_to_shared(wb);
    uint32_t wx_sh = (uint32_t)__cvta_generic_to_shared(wx);

    auto tile_meta = [&](int t, int& e, int& rs, int& v) {
        e = 0;
        #pragma unroll
        for (int j = 1; j < EE; j++)
            if (t >= g_tileOff[j]) e = j;
        int ti = t - g_tileOff[e];
        rs = g_offsets[e] + ti * M_TILE;
        v = g_offsets[e + 1] - rs;
        if (v > M_TILE) v = M_TILE;
    };
    auto stage_w = [&](int e, int par) {
        const float* W1e = W1 + (size_t)e * WB_FLOATS;  // [d][h], h contiguous
        uint32_t dst = wb_sh + (uint32_t)par * WB_BYTES;
        #pragma unroll
        for (int m = 0; m < 2; m++) {
            int s = tid + m * THREADS;
            cp_async16(dst + (uint32_t)s * 16u, W1e + s * 4);
        }
        uint32_t xdst = wx_sh + (uint32_t)par * 160u;
        if (tid < 4)       cp_async16(xdst + tid * 16u, b1 + e * HH + tid * 4);
        else if (tid < 8)  cp_async16(xdst + 64u + (tid - 4) * 16u, W2 + e * HH + (tid - 4) * 4);
        else if (tid == 8) cp_async4(xdst + 128u, b2 + e);
    };
    // stage 8-d chunk c2 of tile rows in sRow[p2] into ring buffer buf
    auto stage_x = [&](int c2, int p2, int buf) {
        const int* rp = sRow + p2 * M_TILE;
        uint32_t bb = xs_sh + (uint32_t)buf * XCHUNK_BYTES;
        const float* xc = x + c2 * CHUNK_D;
        #pragma unroll
        for (int m = 0; m < 8; m++) {
            int idx = tid + m * THREADS;
            int r = idx >> 1, s = idx & 1;
            int row = rp[r];
            uint32_t dst = bb + (uint32_t)(r * 32) + (uint32_t)((((s + (r >> 2)) & 1) << 4));
            cp_async16(dst, xc + (size_t)row * DD + s * 4);
        }
    };

    // constant per-thread addressing: rows tid + k*256, 32B row stride
    uint32_t roff[RPT];
    #pragma unroll
    for (int k = 0; k < RPT; k++) roff[k] = (uint32_t)(tid + k * THREADS) * 32u;
    int pk = (tid >> 2) & 1;   // same for all k (k*256>>2 is even)

    // ---- prologue ----
    int eC, rsC, vC;
    tile_meta(t0, eC, rsC, vC);
    #pragma unroll
    for (int k = 0; k < RPT; k++) {
        int r = tid + k * THREADS;
        int idx = (r < vC) ? r : 0;
        sRow[(t0 & 1) * M_TILE + r] = g_perm[rsC + idx];
    }
    __syncthreads();

    int eW0 = -1, eW1 = -1;
    {
        int par0 = t0 & 1;
        stage_w(eC, par0);
        if (par0) eW1 = eC; else eW0 = eC;
        stage_x(0, par0, 0); CP_COMMIT();
        stage_x(1, par0, 1); CP_COMMIT();
        stage_x(2, par0, 2); CP_COMMIT();
        stage_x(3, par0, 3); CP_COMMIT();
    }

    unsigned long long acc[RPT][8];
    int eN = eC, rsN = 0, vN = vC;
    int rrN[RPT];

    int nChunk = (t1 - t0) * NPHASE;
    for (int j = 0; j < nChunk; j++) {
        int i = t0 + (j >> 4);
        int c = j & 15;
        int par = i & 1;

        if (c == 0 && (i + 1) < t1) {
            tile_meta(i + 1, eN, rsN, vN);
            #pragma unroll
            for (int k = 0; k < RPT; k++) {
                int r = tid + k * THREADS;
                int idx = (r < vN) ? r : 0;
                rrN[k] = g_perm[rsN + idx];
            }
        }
        if (c == 1 && (i + 1) < t1) {
            #pragma unroll
            for (int k = 0; k < RPT; k++)
                sRow[((i + 1) & 1) * M_TILE + tid + k * THREADS] = rrN[k];
        }

        // stage chunk j+LOOK
        int j2 = j + LOOK;
        if (j2 < nChunk) {
            int i2 = t0 + (j2 >> 4);
            int c2 = j2 & 15;
            int p2 = i2 & 1;
            if (c2 == 0 && i2 != i) {
                int eOld = p2 ? eW1 : eW0;
                if (eN != eOld) {
                    stage_w(eN, p2);
                    if (p2) eW1 = eN; else eW0 = eN;
                }
            }
            stage_x(c2, p2, j2 % RING);
        }
        CP_COMMIT();
        CP_WAIT4();          // chunk j (and older) complete; 4 groups in flight
        __syncthreads();

        if (c == 0) {
            #pragma unroll
            for (int k = 0; k < RPT; k++)
                #pragma unroll
                for (int p = 0; p < 8; p++) acc[k][p] = 0ULL;
        }

        // ---- compute chunk: 8 d x 4 rows x 16 h ----
        {
            uint32_t xb = xs_sh + (uint32_t)(j % RING) * XCHUNK_BYTES;
            uint32_t wd = wb_sh + (uint32_t)par * WB_BYTES + (uint32_t)(c * CHUNK_D * HH * 4);
            #pragma unroll
            for (int g = 0; g < 2; g++) {
                float4 xv[RPT];
                #pragma unroll
                for (int k = 0; k < RPT; k++) {
                    uint32_t a = xb + roff[k] + (uint32_t)(((g + pk) & 1) << 4);
                    asm("ld.shared.v4.f32 {%0,%1,%2,%3}, [%4];"
                        : "=f"(xv[k].x), "=f"(xv[k].y), "=f"(xv[k].z), "=f"(xv[k].w)
                        : "r"(a));
                }
                #pragma unroll
                for (int dd = 0; dd < 4; dd++) {
                    unsigned long long w[8];
                    uint32_t wa = wd + (uint32_t)((g * 4 + dd) << 6);
                    asm("ld.shared.v2.b64 {%0,%1}, [%2];" : "=l"(w[0]), "=l"(w[1]) : "r"(wa));
                    asm("ld.shared.v2.b64 {%0,%1}, [%2];" : "=l"(w[2]), "=l"(w[3]) : "r"(wa + 16));
                    asm("ld.shared.v2.b64 {%0,%1}, [%2];" : "=l"(w[4]), "=l"(w[5]) : "r"(wa + 32));
                    asm("ld.shared.v2.b64 {%0,%1}, [%2];" : "=l"(w[6]), "=l"(w[7]) : "r"(wa + 48));
                    #pragma unroll
                    for (int k = 0; k < RPT; k++) {
                        float xf = (dd == 0) ? xv[k].x : (dd == 1) ? xv[k].y
                                 : (dd == 2) ? xv[k].z : xv[k].w;
                        unsigned long long xd = bcast2(xf);
                        FMA2(acc[k][0], xd, w[0]);
                        FMA2(acc[k][1], xd, w[1]);
                        FMA2(acc[k][2], xd, w[2]);
                        FMA2(acc[k][3], xd, w[3]);
                        FMA2(acc[k][4], xd, w[4]);
                        FMA2(acc[k][5], xd, w[5]);
                        FMA2(acc[k][6], xd, w[6]);
                        FMA2(acc[k][7], xd, w[7]);
                    }
                }
            }
        }

        // ---- tile epilogue ----
        if (c == 15) {
            const float* wxp = wx + par * 40;
            float b1r[HH], w2r[HH];
            #pragma unroll
            for (int h = 0; h < HH; h++) { b1r[h] = wxp[h]; w2r[h] = wxp[16 + h]; }
            float b2v = wxp[32];
            const int* rp = sRow + par * M_TILE;
            #pragma unroll
            for (int k = 0; k < RPT; k++) {
                int r = tid + k * THREADS;
                float y = b2v;
                #pragma unroll
                for (int p = 0; p < 8; p++) {
                    float lo = __uint_as_float((uint32_t)acc[k][p]);
                    float hi = __uint_as_float((uint32_t)(acc[k][p] >> 32));
                    y = fmaf(fmaxf(lo + b1r[2 * p], 0.0f), w2r[2 * p], y);
                    y = fmaf(fmaxf(hi + b1r[2 * p + 1], 0.0f), w2r[2 * p + 1], y);
                }
                if (r < vC) out[rp[r]] = fmaxf(y, 0.0f);
            }
            eC = eN; vC = vN;
        }
    }
}

extern "C" void kernel_launch(void* const* d_in, const int* in_sizes, int n_in,
                              void* d_out, int out_size)
{
    const float* x   = (const float*)d_in[0];
    const int*   sid = (const int*)d_in[1];
    const float* W1  = (const float*)d_in[2];
    const float* b1  = (const float*)d_in[3];
    const float* W2  = (const float*)d_in[4];
    const float* b2  = (const float*)d_in[5];
    float* out = (float*)d_out;

    static bool attr_set = false;
    if (!attr_set) {
        cudaFuncSetAttribute(k_main, cudaFuncAttributeMaxDynamicSharedMemorySize, SMEM_BYTES);
        attr_set = true;
    }

    k_hist<<<NROWS / 4096, 1024>>>(sid);
    k_scan<<<1, 32>>>();
    k_scatter<<<NROWS / 1024, 1024>>>(sid);
    k_main<<<GRID_MAIN, THREADS, SMEM_BYTES>>>(x, W1, b1, W2, b2, out);
}

// round 8
// speedup vs baseline: 1.2218x; 1.2218x over previous
#include <cuda_runtime.h>
#include <cuda_bf16.h>
#include <cstdint>

#define NROWS 262144
#define DD 128
#define HH 16
#define EE 21

#define THREADS 256
#define M_TILE 128                 // rows per slab (8 warps x 16 rows)
#define GRID_MAIN 148

#define XSLAB_BYTES (M_TILE * DD * 4)         // 65536
#define WSTRIDE 20                            // words per d-row: 16 W1 + 4 extras
#define WSLAB_BYTES (DD * WSTRIDE * 4)        // 10240
#define SMEM_BYTES (3 * XSLAB_BYTES + 3 * WSLAB_BYTES + 3 * M_TILE * 4)  // 228864

__device__ int g_counts[EE];
__device__ int g_cursor[EE];
__device__ int g_offsets[EE + 1];
__device__ int g_tileOff[EE + 1];
__device__ int g_numTiles;
__device__ int g_perm[NROWS];
__device__ float g_Wsplit[EE][DD * HH];   // tf32-rounded W1, [d][h] contiguous

// ---------------- K1: histogram (int4 vectorized) ----------------
__global__ void k_hist(const int* __restrict__ sid) {
    __shared__ int sh[EE];
    int tid = threadIdx.x;
    if (tid < EE) sh[tid] = 0;
    __syncthreads();
    int4 v = ((const int4*)sid)[blockIdx.x * blockDim.x + tid];
    atomicAdd(&sh[v.x], 1);
    atomicAdd(&sh[v.y], 1);
    atomicAdd(&sh[v.z], 1);
    atomicAdd(&sh[v.w], 1);
    __syncthreads();
    if (tid < EE) atomicAdd(&g_counts[tid], sh[tid]);
}

// ---------------- K2: block0 = warp scan; blocks 1..21 = tf32 weight prep ----
__global__ void k_scan_prep(const float* __restrict__ W1) {
    if (blockIdx.x == 0) {
        if (threadIdx.x < 32) {
            int t = threadIdx.x;
            int c  = (t < EE) ? g_counts[t] : 0;
            int tl = (c + M_TILE - 1) / M_TILE;
            int ic = c, it = tl;
            #pragma unroll
            for (int d = 1; d < 32; d <<= 1) {
                int vc = __shfl_up_sync(0xFFFFFFFFu, ic, d);
                int vt = __shfl_up_sync(0xFFFFFFFFu, it, d);
                if (t >= d) { ic += vc; it += vt; }
            }
            if (t < EE) {
                g_offsets[t] = ic - c;
                g_cursor[t]  = ic - c;
                g_tileOff[t] = it - tl;
                g_counts[t]  = 0;
            }
            int totC = __shfl_sync(0xFFFFFFFFu, ic, EE - 1);
            int totT = __shfl_sync(0xFFFFFFFFu, it, EE - 1);
            if (t == 0) {
                g_offsets[EE] = totC;
                g_tileOff[EE] = totT;
                g_numTiles = totT;
            }
        }
    } else {
        int e = blockIdx.x - 1;
        for (int i = threadIdx.x; i < DD * HH; i += blockDim.x) {
            float w = W1[e * DD * HH + i];
            uint32_t hb;
            asm("cvt.rna.tf32.f32 %0, %1;" : "=r"(hb) : "f"(w));
            g_Wsplit[e][i] = __uint_as_float(hb);
        }
    }
}

// ---------------- K3: scatter ----------------
__global__ void k_scatter(const int* __restrict__ sid) {
    __shared__ int sHist[EE];
    __shared__ int sBase[EE];
    int tid = threadIdx.x;
    if (tid < EE) sHist[tid] = 0;
    __syncthreads();
    int gid = blockIdx.x * blockDim.x + tid;
    int e = sid[gid];
    int myIdx = atomicAdd(&sHist[e], 1);
    __syncthreads();
    if (tid < EE) sBase[tid] = atomicAdd(&g_cursor[tid], sHist[tid]);
    __syncthreads();
    g_perm[sBase[e] + myIdx] = gid;
}

// ---------------- K4: tf32-MMA persistent expert MLP ----------------
__device__ __forceinline__ void cp_async16(uint32_t dst, const void* src) {
    asm volatile("cp.async.cg.shared.global [%0], [%1], 16;\n" :: "r"(dst), "l"(src));
}
__device__ __forceinline__ void cp_async4(uint32_t dst, const void* src) {
    asm volatile("cp.async.ca.shared.global [%0], [%1], 4;\n" :: "r"(dst), "l"(src));
}
#define CP_COMMIT() asm volatile("cp.async.commit_group;" ::: "memory")
#define CP_WAIT2()  asm volatile("cp.async.wait_group 2;" ::: "memory")

#define MMA_TF32(C0,C1,C2,C3, A0,A1,A2,A3, B0,B1)                                  \
    asm volatile("mma.sync.aligned.m16n8k8.row.col.f32.tf32.tf32.f32 "             \
        "{%0,%1,%2,%3}, {%4,%5,%6,%7}, {%8,%9}, {%0,%1,%2,%3};"                    \
        : "+f"(C0), "+f"(C1), "+f"(C2), "+f"(C3)                                   \
        : "r"(A0), "r"(A1), "r"(A2), "r"(A3), "r"(B0), "r"(B1))

__global__ __launch_bounds__(THREADS, 1)
void k_main(const float* __restrict__ x,
            const float* __restrict__ W1,
            const float* __restrict__ b1,
            const float* __restrict__ W2,
            const float* __restrict__ b2,
            float* __restrict__ out)
{
    extern __shared__ float smem[];
    float* xs = smem;                                    // 3 x 64KB slabs (swizzled)
    float* wb = xs + 3 * (XSLAB_BYTES / 4);              // 3 x [128 d][20]
    int* sRow = (int*)(wb + 3 * (WSLAB_BYTES / 4));      // 3 x 128

    int nT = g_numTiles;
    int q = (nT + GRID_MAIN - 1) / GRID_MAIN;
    int t0 = blockIdx.x * q;
    int t1 = t0 + q; if (t1 > nT) t1 = nT;
    int n = t1 - t0;
    if (n <= 0) return;

    int tid = threadIdx.x;
    int wid = tid >> 5;
    int t = tid & 31;
    uint32_t xs_sh = (uint32_t)__cvta_generic_to_shared(xs);
    uint32_t wb_sh = (uint32_t)__cvta_generic_to_shared(wb);

    auto tile_meta = [&](int tt, int& e, int& rs, int& v) {
        e = 0;
        #pragma unroll
        for (int j = 1; j < EE; j++)
            if (tt >= g_tileOff[j]) e = j;
        int ti = tt - g_tileOff[e];
        rs = g_offsets[e] + ti * M_TILE;
        v = g_offsets[e + 1] - rs;
        if (v > M_TILE) v = M_TILE;
    };
    auto stage_w = [&](int e, int slot) {
        uint32_t dst = wb_sh + (uint32_t)slot * WSLAB_BYTES;
        const float* Ws = g_Wsplit[e];
        #pragma unroll
        for (int m = 0; m < 2; m++) {
            int idx = tid + m * THREADS;
            int d = idx >> 2, s = idx & 3;
            cp_async16(dst + (uint32_t)(d * 80 + s * 16), Ws + d * 16 + s * 4);
        }
        if (tid < 4)       cp_async16(dst + (uint32_t)(tid * 80 + 64), b1 + e * HH + tid * 4);
        else if (tid < 8)  cp_async16(dst + (uint32_t)(tid * 80 + 64), W2 + e * HH + (tid - 4) * 4);
        else if (tid == 8) cp_async4(dst + (uint32_t)(8 * 80 + 64), b2 + e);
    };
    auto stage_x = [&](int slot, const int* rp) {
        uint32_t bb = xs_sh + (uint32_t)slot * XSLAB_BYTES;
        #pragma unroll
        for (int m = 0; m < 16; m++) {
            int idx = tid + m * THREADS;       // 4096 16B chunks
            int r = idx >> 5, s = idx & 31;
            int row = rp[r];
            uint32_t dst = bb + (uint32_t)(r * 512) + (uint32_t)(((s ^ (r & 7)) << 4));
            cp_async16(dst, x + (size_t)row * DD + s * 4);
        }
    };

    // ---- prologue: slabs 0 and 1 ----
    int eSlot0 = -1, eSlot1 = -1, eSlot2 = -1;
    {
        int e0, rs0, v0;
        tile_meta(t0, e0, rs0, v0);
        if (tid < M_TILE) sRow[tid] = g_perm[rs0 + ((tid < v0) ? tid : 0)];
        if (n > 1) {
            int e1, rs1, v1;
            tile_meta(t0 + 1, e1, rs1, v1);
            if (tid < M_TILE) sRow[M_TILE + tid] = g_perm[rs1 + ((tid < v1) ? tid : 0)];
            eSlot1 = e1;
        }
        eSlot0 = e0;
        __syncthreads();
        stage_w(eSlot0, 0);
        stage_x(0, sRow);
        CP_COMMIT();
        if (n > 1) {
            if (eSlot1 != eSlot0) stage_w(eSlot1, 1);
            else eSlot1 = eSlot0;   // content identical; slot1 never staged — stage anyway:
            if (eSlot1 == eSlot0 && true) stage_w(eSlot1, 1);  // always stage slot1 once
            stage_x(1, sRow + M_TILE);
        }
        CP_COMMIT();
    }

    // prefetch perm rows for slab 2
    int rr = 0;
    if (n > 2) {
        int e2, rs2, v2;
        tile_meta(t0 + 2, e2, rs2, v2);
        if (tid < M_TILE) rr = g_perm[rs2 + ((tid < v2) ? tid : 0)];
    }

    // A-frag addressing (constant per thread)
    int r1l = wid * 16 + (t >> 2);
    uint32_t swz = (uint32_t)((r1l & 7) << 2);
    uint32_t xrow_off = (uint32_t)(r1l * 512);
    uint32_t b_lane = (uint32_t)(((t & 3) * WSTRIDE + (t >> 2)) * 4);

    for (int j = 0; j < n; j++) {
        int slot  = j % 3;
        int slot2 = (j + 2) % 3;

        __syncthreads();                              // prior compute done; slot2 free
        if (j + 2 < n && tid < M_TILE) sRow[slot2 * M_TILE + tid] = rr;
        __syncthreads();

        if (j + 2 < n) {
            int e2, rs2, v2;
            tile_meta(t0 + j + 2, e2, rs2, v2);
            int eCur = (slot2 == 0) ? eSlot0 : (slot2 == 1) ? eSlot1 : eSlot2;
            if (e2 != eCur) {
                stage_w(e2, slot2);
                if (slot2 == 0) eSlot0 = e2; else if (slot2 == 1) eSlot1 = e2; else eSlot2 = e2;
            }
            stage_x(slot2, sRow + slot2 * M_TILE);
        }
        CP_COMMIT();

        // prefetch perm rows for slab j+3 (overlaps the wait)
        if (j + 3 < n) {
            int e3, rs3, v3;
            tile_meta(t0 + j + 3, e3, rs3, v3);
            if (tid < M_TILE) rr = g_perm[rs3 + ((tid < v3) ? tid : 0)];
        }

        CP_WAIT2();
        __syncthreads();

        // ---- compute slab j: 128 rows x 128 d -> 16 h, tf32 MMA (x hi+lo) ----
        uint32_t xb = xs_sh + (uint32_t)slot * XSLAB_BYTES + xrow_off;
        uint32_t wbase = wb_sh + (uint32_t)slot * WSLAB_BYTES + b_lane;
        float c00 = 0.f, c01 = 0.f, c02 = 0.f, c03 = 0.f;   // h 0..7
        float c10 = 0.f, c11 = 0.f, c12 = 0.f, c13 = 0.f;   // h 8..15

        #pragma unroll
        for (int k = 0; k < 16; k++) {
            uint32_t c0 = (uint32_t)(8 * k + (t & 3));
            uint32_t A0a = xb + ((c0 ^ swz) << 2);
            uint32_t A2a = A0a ^ 16u;
            float f0, f1, f2, f3;
            asm("ld.shared.f32 %0, [%1];" : "=f"(f0) : "r"(A0a));
            asm("ld.shared.f32 %0, [%1];" : "=f"(f1) : "r"(A0a + 4096));
            asm("ld.shared.f32 %0, [%1];" : "=f"(f2) : "r"(A2a));
            asm("ld.shared.f32 %0, [%1];" : "=f"(f3) : "r"(A2a + 4096));
            uint32_t h0, h1, h2, h3;
            asm("cvt.rna.tf32.f32 %0, %1;" : "=r"(h0) : "f"(f0));
            asm("cvt.rna.tf32.f32 %0, %1;" : "=r"(h1) : "f"(f1));
            asm("cvt.rna.tf32.f32 %0, %1;" : "=r"(h2) : "f"(f2));
            asm("cvt.rna.tf32.f32 %0, %1;" : "=r"(h3) : "f"(f3));
            uint32_t l0 = __float_as_uint(f0 - __uint_as_float(h0));
            uint32_t l1 = __float_as_uint(f1 - __uint_as_float(h1));
            uint32_t l2 = __float_as_uint(f2 - __uint_as_float(h2));
            uint32_t l3 = __float_as_uint(f3 - __uint_as_float(h3));

            uint32_t wk = wbase + (uint32_t)(k * 8 * WSTRIDE * 4);
            uint32_t b0, b1r, b2r, b3;
            asm("ld.shared.b32 %0, [%1];" : "=r"(b0)  : "r"(wk));          // B[d=8k+t%4][h=t/4]
            asm("ld.shared.b32 %0, [%1];" : "=r"(b1r) : "r"(wk + 320));    // +4 d-rows
            asm("ld.shared.b32 %0, [%1];" : "=r"(b2r) : "r"(wk + 32));     // +8 h-cols
            asm("ld.shared.b32 %0, [%1];" : "=r"(b3)  : "r"(wk + 352));

            MMA_TF32(c00, c01, c02, c03, h0, h1, h2, h3, b0, b1r);
            MMA_TF32(c00, c01, c02, c03, l0, l1, l2, l3, b0, b1r);
            MMA_TF32(c10, c11, c12, c13, h0, h1, h2, h3, b2r, b3);
            MMA_TF32(c10, c11, c12, c13, l0, l1, l2, l3, b2r, b3);
        }

        // ---- epilogue: relu, dot w2, quad-reduce, store ----
        {
            int ej, rsj, vj;
            tile_meta(t0 + j, ej, rsj, vj);
            uint32_t wxb = wb_sh + (uint32_t)slot * WSLAB_BYTES;
            int qn = t & 3;
            float b1a[4], w2a[4];
            #pragma unroll
            for (int u = 0; u < 4; u++) {
                int h = (u < 2) ? (2 * qn + u) : (8 + 2 * qn + (u - 2));
                float bv, wv;
                asm("ld.shared.f32 %0, [%1];" : "=f"(bv)
                    : "r"(wxb + (uint32_t)(((h >> 2) * WSTRIDE + 16 + (h & 3)) * 4)));
                asm("ld.shared.f32 %0, [%1];" : "=f"(wv)
                    : "r"(wxb + (uint32_t)(((4 + (h >> 2)) * WSTRIDE + 16 + (h & 3)) * 4)));
                b1a[u] = bv; w2a[u] = wv;
            }
            float b2v;
            asm("ld.shared.f32 %0, [%1];" : "=f"(b2v)
                : "r"(wxb + (uint32_t)((8 * WSTRIDE + 16) * 4)));

            float p1 = fmaxf(c00 + b1a[0], 0.f) * w2a[0] + fmaxf(c01 + b1a[1], 0.f) * w2a[1]
                     + fmaxf(c10 + b1a[2], 0.f) * w2a[2] + fmaxf(c11 + b1a[3], 0.f) * w2a[3];
            float p2 = fmaxf(c02 + b1a[0], 0.f) * w2a[0] + fmaxf(c03 + b1a[1], 0.f) * w2a[1]
                     + fmaxf(c12 + b1a[2], 0.f) * w2a[2] + fmaxf(c13 + b1a[3], 0.f) * w2a[3];
            p1 += __shfl_xor_sync(0xFFFFFFFFu, p1, 1);
            p1 += __shfl_xor_sync(0xFFFFFFFFu, p1, 2);
            p2 += __shfl_xor_sync(0xFFFFFFFFu, p2, 1);
            p2 += __shfl_xor_sync(0xFFFFFFFFu, p2, 2);
            if (qn == 0) {
                const int* rp = sRow + slot * M_TILE;
                int r1 = r1l, r2 = r1l + 8;
                if (r1 < vj) out[rp[r1]] = fmaxf(p1 + b2v, 0.f);
                if (r2 < vj) out[rp[r2]] = fmaxf(p2 + b2v, 0.f);
            }
        }
    }
}

extern "C" void kernel_launch(void* const* d_in, const int* in_sizes, int n_in,
                              void* d_out, int out_size)
{
    const float* x   = (const float*)d_in[0];
    const int*   sid = (const int*)d_in[1];
    const float* W1  = (const float*)d_in[2];
    const float* b1  = (const float*)d_in[3];
    const float* W2  = (const float*)d_in[4];
    const float* b2  = (const float*)d_in[5];
    float* out = (float*)d_out;

    static bool attr_set = false;
    if (!attr_set) {
        cudaFuncSetAttribute(k_main, cudaFuncAttributeMaxDynamicSharedMemorySize, SMEM_BYTES);
        attr_set = true;
    }

    k_hist<<<NROWS / 4096, 1024>>>(sid);
    k_scan_prep<<<1 + EE, 128>>>(W1);
    k_scatter<<<NROWS / 1024, 1024>>>(sid);
    k_main<<<GRID_MAIN, THREADS, SMEM_BYTES>>>(x, W1, b1, W2, b2, out);
}